// round 4
// baseline (speedup 1.0000x reference)
#include <cuda_runtime.h>

#define Z0f 10.0f
#define EPSf 1e-6f
#define AP_R2 400.0f   // (DIAMETER*0.5)^2 = 20^2

// Process 4 rays per thread with fully vectorized float4 traffic.
// P: [N,3] f32, V: [N,3] f32, out: [N,6] f32.
__global__ __launch_bounds__(256)
void refract_quad_kernel(const float4* __restrict__ P4,
                         const float4* __restrict__ V4,
                         const float* __restrict__ Rp,
                         const float* __restrict__ n1p,
                         const float* __restrict__ n2p,
                         float4* __restrict__ out4,
                         int nQuads)
{
    int i = blockIdx.x * blockDim.x + threadIdx.x;
    if (i >= nQuads) return;

    const float R0   = Rp[0];
    const float eta  = n1p[0] / n2p[0];
    const float Cx   = Z0f + R0;
    const float invR = 1.0f / R0;
    const float eta2 = eta * eta;

    // Batched front loads: 6 independent float4 loads -> MLP 6
    float4 p0 = P4[3*i + 0];
    float4 p1 = P4[3*i + 1];
    float4 p2 = P4[3*i + 2];
    float4 v0 = V4[3*i + 0];
    float4 v1 = V4[3*i + 1];
    float4 v2 = V4[3*i + 2];

    float pf[12] = {p0.x,p0.y,p0.z,p0.w, p1.x,p1.y,p1.z,p1.w, p2.x,p2.y,p2.z,p2.w};
    float vf[12] = {v0.x,v0.y,v0.z,v0.w, v1.x,v1.y,v1.z,v1.w, v2.x,v2.y,v2.z,v2.w};
    float of[24];

    #pragma unroll
    for (int j = 0; j < 4; j++) {
        float px = pf[3*j+0], py = pf[3*j+1], pz = pf[3*j+2];
        float vx = vf[3*j+0], vy = vf[3*j+1], vz = vf[3*j+2];

        // sphere intersection: t^2 + b t + c = 0  (|V| = 1)
        float pcx = px - Cx, pcy = py, pcz = pz;
        float b = 2.0f * (vx*pcx + vy*pcy + vz*pcz);
        float c = pcx*pcx + pcy*pcy + pcz*pcz - R0*R0;
        float disc = b*b - 4.0f*c;
        float sd = sqrtf(fmaxf(disc, 0.0f));
        float t1 = (-b - sd) * 0.5f;
        float t2 = (-b + sd) * 0.5f;
        float t  = (t1 > EPSf) ? t1 : t2;
        bool hit = (disc >= 0.0f) && (t > EPSf);

        // collision point + aperture clip
        float qx = px + t*vx, qy = py + t*vy, qz = pz + t*vz;
        float r2 = qy*qy + qz*qz;
        hit = hit && (r2 <= AP_R2);

        // surface normal, oriented against incoming ray
        float nx = (qx - Cx) * invR, ny = qy * invR, nz = qz * invR;
        float ndotv = nx*vx + ny*vy + nz*vz;
        if (ndotv > 0.0f) { nx = -nx; ny = -ny; nz = -nz; }

        // Snell refraction (vector form)
        float cosi  = -(nx*vx + ny*vy + nz*vz);
        float sin2t = eta2 * (1.0f - cosi*cosi);
        bool refract_ok = (sin2t <= 1.0f);
        float cost = sqrtf(fmaxf(1.0f - sin2t, 0.0f));
        float k = eta*cosi - cost;
        float Tx = eta*vx + k*nx;
        float Ty = eta*vy + k*ny;
        float Tz = eta*vz + k*nz;

        bool valid = hit && refract_ok;
        of[6*j+0] = valid ? qx : 0.0f;
        of[6*j+1] = valid ? qy : 0.0f;
        of[6*j+2] = valid ? qz : 0.0f;
        of[6*j+3] = valid ? Tx : 0.0f;
        of[6*j+4] = valid ? Ty : 0.0f;
        of[6*j+5] = valid ? Tz : 0.0f;
    }

    #pragma unroll
    for (int w = 0; w < 6; w++) {
        out4[6*i + w] = make_float4(of[4*w+0], of[4*w+1], of[4*w+2], of[4*w+3]);
    }
}

// Scalar tail for N % 4 != 0 (not hit for N = 8388608, but keep it general).
__global__ void refract_tail_kernel(const float* __restrict__ P,
                                    const float* __restrict__ V,
                                    const float* __restrict__ Rp,
                                    const float* __restrict__ n1p,
                                    const float* __restrict__ n2p,
                                    float* __restrict__ out,
                                    int start, int N)
{
    int n = start + blockIdx.x * blockDim.x + threadIdx.x;
    if (n >= N) return;

    const float R0   = Rp[0];
    const float eta  = n1p[0] / n2p[0];
    const float Cx   = Z0f + R0;
    const float invR = 1.0f / R0;

    float px = P[3*n+0], py = P[3*n+1], pz = P[3*n+2];
    float vx = V[3*n+0], vy = V[3*n+1], vz = V[3*n+2];

    float pcx = px - Cx, pcy = py, pcz = pz;
    float b = 2.0f * (vx*pcx + vy*pcy + vz*pcz);
    float c = pcx*pcx + pcy*pcy + pcz*pcz - R0*R0;
    float disc = b*b - 4.0f*c;
    float sd = sqrtf(fmaxf(disc, 0.0f));
    float t1 = (-b - sd) * 0.5f;
    float t2 = (-b + sd) * 0.5f;
    float t  = (t1 > EPSf) ? t1 : t2;
    bool hit = (disc >= 0.0f) && (t > EPSf);

    float qx = px + t*vx, qy = py + t*vy, qz = pz + t*vz;
    float r2 = qy*qy + qz*qz;
    hit = hit && (r2 <= AP_R2);

    float nx = (qx - Cx) * invR, ny = qy * invR, nz = qz * invR;
    float ndotv = nx*vx + ny*vy + nz*vz;
    if (ndotv > 0.0f) { nx = -nx; ny = -ny; nz = -nz; }

    float cosi  = -(nx*vx + ny*vy + nz*vz);
    float sin2t = eta*eta * (1.0f - cosi*cosi);
    bool refract_ok = (sin2t <= 1.0f);
    float cost = sqrtf(fmaxf(1.0f - sin2t, 0.0f));
    float k = eta*cosi - cost;

    bool valid = hit && refract_ok;
    out[6*n+0] = valid ? qx : 0.0f;
    out[6*n+1] = valid ? qy : 0.0f;
    out[6*n+2] = valid ? qz : 0.0f;
    out[6*n+3] = valid ? (eta*vx + k*nx) : 0.0f;
    out[6*n+4] = valid ? (eta*vy + k*ny) : 0.0f;
    out[6*n+5] = valid ? (eta*vz + k*nz) : 0.0f;
}

extern "C" void kernel_launch(void* const* d_in, const int* in_sizes, int n_in,
                              void* d_out, int out_size)
{
    const float* P  = (const float*)d_in[0];
    const float* V  = (const float*)d_in[1];
    const float* R  = (const float*)d_in[2];
    const float* n1 = (const float*)d_in[3];
    const float* n2 = (const float*)d_in[4];
    float* out = (float*)d_out;

    int N = in_sizes[0] / 3;       // rays
    int nQuads = N / 4;
    int tail_start = nQuads * 4;

    if (nQuads > 0) {
        int threads = 256;
        int blocks = (nQuads + threads - 1) / threads;
        refract_quad_kernel<<<blocks, threads>>>(
            (const float4*)P, (const float4*)V, R, n1, n2, (float4*)out, nQuads);
    }
    if (tail_start < N) {
        int rem = N - tail_start;
        refract_tail_kernel<<<(rem + 255) / 256, 256>>>(
            P, V, R, n1, n2, out, tail_start, N);
    }
}

// round 5
// speedup vs baseline: 1.0583x; 1.0583x over previous
#include <cuda_runtime.h>

#define Z0f 10.0f
#define EPSf 1e-6f
#define AP_R2 400.0f   // (DIAMETER*0.5)^2

// One ray per thread, 256 rays per block, smem-staged fully vectorized I/O.
// P: [N,3] f32, V: [N,3] f32, out: [N,6] f32.
__global__ __launch_bounds__(256)
void refract_smem_kernel(const float4* __restrict__ P4,
                         const float4* __restrict__ V4,
                         const float* __restrict__ Rp,
                         const float* __restrict__ n1p,
                         const float* __restrict__ n2p,
                         float4* __restrict__ out4)
{
    __shared__ float sIn[1536];   // [0:768) = P floats, [768:1536) = V floats
    __shared__ float sOut[1536];  // 256 rays * 6 floats

    const int tid = threadIdx.x;
    const long blk = blockIdx.x;

    // ---- stage-in: 192 float4 of P + 192 float4 of V, streaming loads ----
    {
        float4* sIn4 = reinterpret_cast<float4*>(sIn);
        const long pbase = blk * 192;
        #pragma unroll
        for (int k = 0; k < 2; k++) {
            int i = tid + k * 256;
            if (i < 384) {
                float4 val = (i < 192) ? __ldcs(&P4[pbase + i])
                                       : __ldcs(&V4[pbase + (i - 192)]);
                sIn4[i] = val;
            }
        }
    }

    const float R0   = Rp[0];
    const float eta  = n1p[0] / n2p[0];
    const float Cx   = Z0f + R0;
    const float invR = 1.0f / R0;
    const float eta2 = eta * eta;

    __syncthreads();

    // ---- compute: one ray per thread ----
    {
        float px = sIn[3*tid + 0], py = sIn[3*tid + 1], pz = sIn[3*tid + 2];
        float vx = sIn[768 + 3*tid + 0], vy = sIn[768 + 3*tid + 1], vz = sIn[768 + 3*tid + 2];

        // sphere intersection: t^2 + b t + c = 0  (|V| = 1)
        float pcx = px - Cx, pcy = py, pcz = pz;
        float b = 2.0f * (vx*pcx + vy*pcy + vz*pcz);
        float c = pcx*pcx + pcy*pcy + pcz*pcz - R0*R0;
        float disc = b*b - 4.0f*c;
        float sd = sqrtf(fmaxf(disc, 0.0f));
        float t1 = (-b - sd) * 0.5f;
        float t2 = (-b + sd) * 0.5f;
        float t  = (t1 > EPSf) ? t1 : t2;
        bool hit = (disc >= 0.0f) && (t > EPSf);

        // collision point + aperture clip
        float qx = px + t*vx, qy = py + t*vy, qz = pz + t*vz;
        float r2 = qy*qy + qz*qz;
        hit = hit && (r2 <= AP_R2);

        // surface normal oriented against the ray
        float nx = (qx - Cx) * invR, ny = qy * invR, nz = qz * invR;
        float ndotv = nx*vx + ny*vy + nz*vz;
        if (ndotv > 0.0f) { nx = -nx; ny = -ny; nz = -nz; }

        // Snell refraction (vector form)
        float cosi  = -(nx*vx + ny*vy + nz*vz);
        float sin2t = eta2 * (1.0f - cosi*cosi);
        bool refract_ok = (sin2t <= 1.0f);
        float cost = sqrtf(fmaxf(1.0f - sin2t, 0.0f));
        float k = eta*cosi - cost;

        bool valid = hit && refract_ok;
        sOut[6*tid + 0] = valid ? qx : 0.0f;
        sOut[6*tid + 1] = valid ? qy : 0.0f;
        sOut[6*tid + 2] = valid ? qz : 0.0f;
        sOut[6*tid + 3] = valid ? (eta*vx + k*nx) : 0.0f;
        sOut[6*tid + 4] = valid ? (eta*vy + k*ny) : 0.0f;
        sOut[6*tid + 5] = valid ? (eta*vz + k*nz) : 0.0f;
    }

    __syncthreads();

    // ---- stage-out: 384 float4 streaming stores ----
    {
        const float4* sOut4 = reinterpret_cast<const float4*>(sOut);
        const long obase = blk * 384;
        #pragma unroll
        for (int k = 0; k < 2; k++) {
            int i = tid + k * 256;
            if (i < 384) __stcs(&out4[obase + i], sOut4[i]);
        }
    }
}

// Scalar tail for leftover rays (N % 256 != 0). Not hit for N = 8388608.
__global__ void refract_tail_kernel(const float* __restrict__ P,
                                    const float* __restrict__ V,
                                    const float* __restrict__ Rp,
                                    const float* __restrict__ n1p,
                                    const float* __restrict__ n2p,
                                    float* __restrict__ out,
                                    int start, int N)
{
    int n = start + blockIdx.x * blockDim.x + threadIdx.x;
    if (n >= N) return;

    const float R0   = Rp[0];
    const float eta  = n1p[0] / n2p[0];
    const float Cx   = Z0f + R0;
    const float invR = 1.0f / R0;

    float px = P[3*n+0], py = P[3*n+1], pz = P[3*n+2];
    float vx = V[3*n+0], vy = V[3*n+1], vz = V[3*n+2];

    float pcx = px - Cx, pcy = py, pcz = pz;
    float b = 2.0f * (vx*pcx + vy*pcy + vz*pcz);
    float c = pcx*pcx + pcy*pcy + pcz*pcz - R0*R0;
    float disc = b*b - 4.0f*c;
    float sd = sqrtf(fmaxf(disc, 0.0f));
    float t1 = (-b - sd) * 0.5f;
    float t2 = (-b + sd) * 0.5f;
    float t  = (t1 > EPSf) ? t1 : t2;
    bool hit = (disc >= 0.0f) && (t > EPSf);

    float qx = px + t*vx, qy = py + t*vy, qz = pz + t*vz;
    float r2 = qy*qy + qz*qz;
    hit = hit && (r2 <= AP_R2);

    float nx = (qx - Cx) * invR, ny = qy * invR, nz = qz * invR;
    float ndotv = nx*vx + ny*vy + nz*vz;
    if (ndotv > 0.0f) { nx = -nx; ny = -ny; nz = -nz; }

    float cosi  = -(nx*vx + ny*vy + nz*vz);
    float sin2t = eta*eta * (1.0f - cosi*cosi);
    bool refract_ok = (sin2t <= 1.0f);
    float cost = sqrtf(fmaxf(1.0f - sin2t, 0.0f));
    float k = eta*cosi - cost;

    bool valid = hit && refract_ok;
    out[6*n+0] = valid ? qx : 0.0f;
    out[6*n+1] = valid ? qy : 0.0f;
    out[6*n+2] = valid ? qz : 0.0f;
    out[6*n+3] = valid ? (eta*vx + k*nx) : 0.0f;
    out[6*n+4] = valid ? (eta*vy + k*ny) : 0.0f;
    out[6*n+5] = valid ? (eta*vz + k*nz) : 0.0f;
}

extern "C" void kernel_launch(void* const* d_in, const int* in_sizes, int n_in,
                              void* d_out, int out_size)
{
    const float* P  = (const float*)d_in[0];
    const float* V  = (const float*)d_in[1];
    const float* R  = (const float*)d_in[2];
    const float* n1 = (const float*)d_in[3];
    const float* n2 = (const float*)d_in[4];
    float* out = (float*)d_out;

    int N = in_sizes[0] / 3;           // rays
    int fullBlocks = N / 256;          // 256 rays per block
    int tail_start = fullBlocks * 256;

    if (fullBlocks > 0) {
        refract_smem_kernel<<<fullBlocks, 256>>>(
            (const float4*)P, (const float4*)V, R, n1, n2, (float4*)out);
    }
    if (tail_start < N) {
        int rem = N - tail_start;
        refract_tail_kernel<<<(rem + 255) / 256, 256>>>(
            P, V, R, n1, n2, out, tail_start, N);
    }
}